// round 9
// baseline (speedup 1.0000x reference)
#include <cuda_runtime.h>
#include <stdint.h>

#define C_DIM  1024
#define D_HEAD 64
#define B_SZ   4
#define T_LEN  4096
#define M_ROWS (B_SZ * T_LEN)
#define NQT    (T_LEN / 128)     // 32 q-tiles (128 rows) per batch
#define CHUNK  8                 // k-tiles (64 wide) per CTA
#define MAXCH  8
#define NCTA_B 144               // sum_{qt=0..31} (qt/4 + 1)

// g_q: [b*T+t][d] tf32 bits, pre-scaled 0.125 (plain layout)
// g_k: [b*T+t][d] tf32 bits, d permuted within 8-blocks (p)
// g_v: [tile][d][s] tf32 bits, per-64-tile transposed, s permuted within 8-blocks
__device__ float g_q[M_ROWS * D_HEAD];
__device__ float g_k[M_ROWS * D_HEAD];
__device__ float g_v[M_ROWS * D_HEAD];

// Split-KV partials
__device__ float g_pO[B_SZ * NQT * MAXCH * 128 * 64];
__device__ float g_pm[B_SZ * NQT * MAXCH * 128];
__device__ float g_pl[B_SZ * NQT * MAXCH * 128];

__device__ __forceinline__ int pperm(int c) {           // 0..7 block permute
    return ((c & 3) << 1) | (c >> 2);                   // slots t,t+4 -> 2t,2t+1
}
__device__ __forceinline__ uint32_t f2tf(float x) {
    uint32_t r; asm("cvt.rna.tf32.f32 %0, %1;" : "=r"(r) : "f"(x)); return r;
}
__device__ __forceinline__ uint32_t fb(float x) { return __float_as_uint(x); }

__device__ __forceinline__ void mma_tf32(float c[4],
    uint32_t a0, uint32_t a1, uint32_t a2, uint32_t a3,
    uint32_t b0, uint32_t b1)
{
    asm volatile(
        "mma.sync.aligned.m16n8k8.row.col.f32.tf32.tf32.f32 "
        "{%0,%1,%2,%3}, {%4,%5,%6,%7}, {%8,%9}, {%0,%1,%2,%3};"
        : "+f"(c[0]), "+f"(c[1]), "+f"(c[2]), "+f"(c[3])
        : "r"(a0), "r"(a1), "r"(a2), "r"(a3), "r"(b0), "r"(b1));
}

__device__ __forceinline__ void cp16(float* dst_smem, const float* src) {
    uint32_t d = (uint32_t)__cvta_generic_to_shared(dst_smem);
    asm volatile("cp.async.ca.shared.global [%0], [%1], 16;" :: "r"(d), "l"(src) : "memory");
}
#define CP_COMMIT() asm volatile("cp.async.commit_group;" ::: "memory")
#define CP_WAIT(N)  asm volatile("cp.async.wait_group %0;" :: "n"(N) : "memory")

// ---------------------------------------------------------------------------
// Projection GEMM (tf32 MMA): 128-row CTAs, 256 threads (round-6 config),
// LDS.64 fragments: Xs k-permuted [128][40], Ws transposed+k-permuted [64][40].
// ---------------------------------------------------------------------------
#define XST 40
#define WST 40

__global__ __launch_bounds__(256) void proj_kernel(
    const float* __restrict__ Xq, const float* __restrict__ Xk, const float* __restrict__ Xv,
    const float* __restrict__ Wq, const float* __restrict__ bq,
    const float* __restrict__ Wk, const float* __restrict__ bk,
    const float* __restrict__ Wv, const float* __restrict__ bv)
{
    __shared__ float Xs[128][XST];   // [m][k-permuted]
    __shared__ float Ws[64][WST];    // [n][k-permuted]

    const float* X; const float* W; const float* bias;
    if (blockIdx.y == 0)      { X = Xq; W = Wq; bias = bq; }
    else if (blockIdx.y == 1) { X = Xk; W = Wk; bias = bk; }
    else                      { X = Xv; W = Wv; bias = bv; }

    const int t    = threadIdx.x;
    const int lane = t & 31;
    const int w    = t >> 5;          // 0..7
    const int g    = lane >> 2;
    const int tig  = lane & 3;
    const int m0   = blockIdx.x * 128;

    const int xrow = t >> 1;          // 0..127
    const int xc0  = (t & 1) * 16;    // 0 or 16
    const int wrow = t >> 3;          // 0..31 (k index)
    const int wc0  = (t & 7) * 8;     // 0..56 (n index)
    const int wkp  = (wrow & ~7) | pperm(wrow & 7);

    float4 xv[4], wv[2];
    #pragma unroll
    for (int i = 0; i < 4; i++)
        xv[i] = *(const float4*)(X + (size_t)(m0 + xrow) * C_DIM + xc0 + 4 * i);
    #pragma unroll
    for (int i = 0; i < 2; i++)
        wv[i] = *(const float4*)(W + (size_t)wrow * D_HEAD + wc0 + 4 * i);

    float c[8][4] = {};

    for (int k0 = 0; k0 < C_DIM; k0 += 32) {
        // Xs: scalar stores, k-permuted columns
        #pragma unroll
        for (int i = 0; i < 4; i++) {
            const int cb = xc0 + 4*i;
            float v4[4] = {xv[i].x, xv[i].y, xv[i].z, xv[i].w};
            #pragma unroll
            for (int e = 0; e < 4; e++) {
                int cc = cb + e;
                Xs[xrow][(cc & ~7) | pperm(cc & 7)] = __uint_as_float(f2tf(v4[e]));
            }
        }
        // Ws: transposed scatter, k-permuted row position
        #pragma unroll
        for (int i = 0; i < 2; i++) {
            float v4[4] = {wv[i].x, wv[i].y, wv[i].z, wv[i].w};
            #pragma unroll
            for (int e = 0; e < 4; e++)
                Ws[wc0 + 4*i + e][wkp] = __uint_as_float(f2tf(v4[e]));
        }
        __syncthreads();

        if (k0 + 32 < C_DIM) {
            #pragma unroll
            for (int i = 0; i < 4; i++)
                xv[i] = *(const float4*)(X + (size_t)(m0 + xrow) * C_DIM + k0 + 32 + xc0 + 4 * i);
            #pragma unroll
            for (int i = 0; i < 2; i++)
                wv[i] = *(const float4*)(W + (size_t)(k0 + 32 + wrow) * D_HEAD + wc0 + 4 * i);
        }

        #pragma unroll
        for (int kc = 0; kc < 4; kc++) {
            float2 alo = *(const float2*)&Xs[w*16 + g    ][kc*8 + 2*tig];
            float2 ahi = *(const float2*)&Xs[w*16 + g + 8][kc*8 + 2*tig];
            uint32_t a0 = fb(alo.x), a1 = fb(ahi.x), a2 = fb(alo.y), a3 = fb(ahi.y);
            #pragma unroll
            for (int nt = 0; nt < 8; nt++) {
                float2 bbv = *(const float2*)&Ws[nt*8 + g][kc*8 + 2*tig];
                mma_tf32(c[nt], a0, a1, a2, a3, fb(bbv.x), fb(bbv.y));
            }
        }
        __syncthreads();
    }

    // Epilogue: bias, then layout-specific store
    const int rlo = m0 + w*16 + g;
    const int rhi = rlo + 8;
    if (blockIdx.y == 0) {
        // Q: plain layout, pre-scale 0.125
        #pragma unroll
        for (int nt = 0; nt < 8; nt++) {
            int col = nt*8 + 2*tig;
            float b0 = bias[col], b1 = bias[col + 1];
            *(float2*)(g_q + (size_t)rlo * D_HEAD + col) =
                make_float2(__uint_as_float(f2tf((c[nt][0] + b0) * 0.125f)),
                            __uint_as_float(f2tf((c[nt][1] + b1) * 0.125f)));
            *(float2*)(g_q + (size_t)rhi * D_HEAD + col) =
                make_float2(__uint_as_float(f2tf((c[nt][2] + b0) * 0.125f)),
                            __uint_as_float(f2tf((c[nt][3] + b1) * 0.125f)));
        }
    } else if (blockIdx.y == 1) {
        // K: d-permuted within 8-blocks
        #pragma unroll
        for (int nt = 0; nt < 8; nt++) {
            int col = nt*8 + 2*tig;
            float b0 = bias[col], b1 = bias[col + 1];
            int p0 = nt*8 + pperm((2*tig) & 7);
            int p1 = nt*8 + pperm((2*tig + 1) & 7);
            g_k[(size_t)rlo * D_HEAD + p0] = __uint_as_float(f2tf(c[nt][0] + b0));
            g_k[(size_t)rlo * D_HEAD + p1] = __uint_as_float(f2tf(c[nt][1] + b1));
            g_k[(size_t)rhi * D_HEAD + p0] = __uint_as_float(f2tf(c[nt][2] + b0));
            g_k[(size_t)rhi * D_HEAD + p1] = __uint_as_float(f2tf(c[nt][3] + b1));
        }
    } else {
        // V: [tile][d][s-permuted] transposed layout
        const int tlo = rlo >> 6, slo = rlo & 63;
        const int thi = rhi >> 6, shi = rhi & 63;
        const int splo = (slo & ~7) | pperm(slo & 7);
        const int sphi = (shi & ~7) | pperm(shi & 7);
        #pragma unroll
        for (int nt = 0; nt < 8; nt++) {
            int col = nt*8 + 2*tig;
            float b0 = bias[col], b1 = bias[col + 1];
            g_v[((size_t)tlo*64 + col    )*64 + splo] = __uint_as_float(f2tf(c[nt][0] + b0));
            g_v[((size_t)tlo*64 + col + 1)*64 + splo] = __uint_as_float(f2tf(c[nt][1] + b1));
            g_v[((size_t)thi*64 + col    )*64 + sphi] = __uint_as_float(f2tf(c[nt][2] + b0));
            g_v[((size_t)thi*64 + col + 1)*64 + sphi] = __uint_as_float(f2tf(c[nt][3] + b1));
        }
    }
}

// ---------------------------------------------------------------------------
// Flash attention partial: 128-row q-tile, 256 threads, split-KV <=8 k-tiles.
// K,V double-buffered cp.async (stride 72 -> conflict-free LDS.64 b-frags),
// dedicated P buffer (stride 68), one __syncthreads per iter.
// ---------------------------------------------------------------------------
#define KST 72
#define VST 72
#define PST 68
#define SMEM_ATTN ((2*64*KST + 2*64*VST + 128*PST) * 4)

__global__ __launch_bounds__(256, 2) void attn_partial_kernel()
{
    extern __shared__ float sm[];
    float* ks[2] = { sm, sm + 64*KST };
    float* vs[2] = { sm + 2*64*KST, sm + 2*64*KST + 64*VST };
    float* ps    = sm + 2*64*KST + 2*64*VST;   // [128][PST]

    const int b = blockIdx.y;
    int idx = NCTA_B - 1 - blockIdx.x;   // heavy q-tiles first
    int grp = 0, base = 0;
    while (idx >= base + 4*(grp+1)) { base += 4*(grp+1); ++grp; }
    int r  = idx - base;
    int qt = 4*grp + r / (grp+1);
    int ci = r % (grp+1);
    const int j0   = ci * CHUNK;
    const int jend = min(j0 + CHUNK, 2*qt + 2);

    const int t    = threadIdx.x;
    const int lane = t & 31;
    const int w    = t >> 5;
    const int g    = lane >> 2;
    const int tig  = lane & 3;
    const int rlo  = w*16 + g;
    const int rhi  = rlo + 8;

    const float* qp = g_q + ((size_t)b * T_LEN + qt * 128) * D_HEAD;
    const float* kb = g_k + (size_t)b * T_LEN * D_HEAD;
    const float* vtb = g_v + (size_t)b * 64 * 64 * 64;   // [tile][d][sp] per batch

    const int row = t >> 2;           // 0..63
    const int c0  = (t & 3) * 16;

    // Prologue: K_j0 + V_j0 one group
    {
        const float* kp = kb + (size_t)(j0*64 + row) * D_HEAD + c0;
        const float* vp = vtb + ((size_t)j0*64 + row) * 64 + c0;
        #pragma unroll
        for (int i = 0; i < 4; i++) cp16(ks[0] + row*KST + c0 + 4*i, kp + 4*i);
        #pragma unroll
        for (int i = 0; i < 4; i++) cp16(vs[0] + row*VST + c0 + 4*i, vp + 4*i);
        CP_COMMIT();
    }

    // Q fragments (tf32 bits, pre-scaled)
    uint32_t qa[8][4];
    #pragma unroll
    for (int kc = 0; kc < 8; kc++) {
        qa[kc][0] = fb(qp[rlo * D_HEAD + kc*8 + tig    ]);
        qa[kc][1] = fb(qp[rhi * D_HEAD + kc*8 + tig    ]);
        qa[kc][2] = fb(qp[rlo * D_HEAD + kc*8 + tig + 4]);
        qa[kc][3] = fb(qp[rhi * D_HEAD + kc*8 + tig + 4]);
    }

    float oc[8][4] = {};
    float m_lo = -1e30f, m_hi = -1e30f, l_lo = 0.f, l_hi = 0.f;

    for (int j = j0; j < jend; j++) {
        const int bufc = (j - j0) & 1;
        float* kcur = ks[bufc];
        float* vcur = vs[bufc];

        CP_WAIT(0);
        __syncthreads();

        if (j + 1 < jend) {
            float* knxt = ks[bufc ^ 1];
            float* vnxt = vs[bufc ^ 1];
            const float* kp = kb + (size_t)((j+1)*64 + row) * D_HEAD + c0;
            const float* vp = vtb + ((size_t)(j+1)*64 + row) * 64 + c0;
            #pragma unroll
            for (int i = 0; i < 4; i++) cp16(knxt + row*KST + c0 + 4*i, kp + 4*i);
            #pragma unroll
            for (int i = 0; i < 4; i++) cp16(vnxt + row*VST + c0 + 4*i, vp + 4*i);
            CP_COMMIT();
        }

        // S = Q @ K^T  (b-frags: one LDS.64 each, conflict-free)
        float sc[8][4] = {};
        #pragma unroll
        for (int kc = 0; kc < 8; kc++) {
            #pragma unroll
            for (int nt = 0; nt < 8; nt++) {
                float2 bbv = *(const float2*)&kcur[(nt*8 + g)*KST + kc*8 + 2*tig];
                mma_tf32(sc[nt], qa[kc][0], qa[kc][1], qa[kc][2], qa[kc][3],
                         fb(bbv.x), fb(bbv.y));
            }
        }

        // Causal mask (k-tiles j >= 2*qt touch the diagonal)
        if (j >= 2*qt) {
            const int co = (j - 2*qt) * 64;
            #pragma unroll
            for (int nt = 0; nt < 8; nt++) {
                int cb = co + nt*8 + 2*tig;
                if (cb     > rlo) sc[nt][0] = -1e30f;
                if (cb + 1 > rlo) sc[nt][1] = -1e30f;
                if (cb     > rhi) sc[nt][2] = -1e30f;
                if (cb + 1 > rhi) sc[nt][3] = -1e30f;
            }
        }

        // Online softmax
        float mx0 = -1e30f, mx1 = -1e30f;
        #pragma unroll
        for (int nt = 0; nt < 8; nt++) {
            mx0 = fmaxf(mx0, fmaxf(sc[nt][0], sc[nt][1]));
            mx1 = fmaxf(mx1, fmaxf(sc[nt][2], sc[nt][3]));
        }
        mx0 = fmaxf(mx0, __shfl_xor_sync(0xffffffffu, mx0, 1));
        mx0 = fmaxf(mx0, __shfl_xor_sync(0xffffffffu, mx0, 2));
        mx1 = fmaxf(mx1, __shfl_xor_sync(0xffffffffu, mx1, 1));
        mx1 = fmaxf(mx1, __shfl_xor_sync(0xffffffffu, mx1, 2));

        float mn0 = fmaxf(m_lo, mx0);
        float mn1 = fmaxf(m_hi, mx1);
        float s0 = 0.f, s1 = 0.f;
        #pragma unroll
        for (int nt = 0; nt < 8; nt++) {
            sc[nt][0] = __expf(sc[nt][0] - mn0); s0 += sc[nt][0];
            sc[nt][1] = __expf(sc[nt][1] - mn0); s0 += sc[nt][1];
            sc[nt][2] = __expf(sc[nt][2] - mn1); s1 += sc[nt][2];
            sc[nt][3] = __expf(sc[nt][3] - mn1); s1 += sc[nt][3];
        }
        s0 += __shfl_xor_sync(0xffffffffu, s0, 1);
        s0 += __shfl_xor_sync(0xffffffffu, s0, 2);
        s1 += __shfl_xor_sync(0xffffffffu, s1, 1);
        s1 += __shfl_xor_sync(0xffffffffu, s1, 2);

        float a0 = __expf(m_lo - mn0);
        float a1 = __expf(m_hi - mn1);
        l_lo = l_lo * a0 + s0;  m_lo = mn0;
        l_hi = l_hi * a1 + s1;  m_hi = mn1;
        #pragma unroll
        for (int nt = 0; nt < 8; nt++) {
            oc[nt][0] *= a0; oc[nt][1] *= a0;
            oc[nt][2] *= a1; oc[nt][3] *= a1;
        }

        // P -> ps (per-warp strip, plain s order)
        {
            float* plo = ps + rlo*PST;
            float* phi = ps + rhi*PST;
            #pragma unroll
            for (int nt = 0; nt < 8; nt++) {
                int cb = nt*8 + 2*tig;
                *(float2*)&plo[cb] = make_float2(__uint_as_float(f2tf(sc[nt][0])),
                                                 __uint_as_float(f2tf(sc[nt][1])));
                *(float2*)&phi[cb] = make_float2(__uint_as_float(f2tf(sc[nt][2])),
                                                 __uint_as_float(f2tf(sc[nt][3])));
            }
        }
        __syncwarp();

        // O += P @ V  (V b-frags: one LDS.64 via transposed+permuted layout)
        #pragma unroll
        for (int kc = 0; kc < 8; kc++) {
            uint32_t pa0 = fb(ps[rlo*PST + kc*8 + tig    ]);
            uint32_t pa1 = fb(ps[rhi*PST + kc*8 + tig    ]);
            uint32_t pa2 = fb(ps[rlo*PST + kc*8 + tig + 4]);
            uint32_t pa3 = fb(ps[rhi*PST + kc*8 + tig + 4]);
            #pragma unroll
            for (int nt = 0; nt < 8; nt++) {
                float2 bbv = *(const float2*)&vcur[(nt*8 + g)*VST + kc*8 + 2*tig];
                mma_tf32(oc[nt], pa0, pa1, pa2, pa3, fb(bbv.x), fb(bbv.y));
            }
        }
    }

    // Write partial + m/l
    const size_t pbase = ((size_t)(b * NQT + qt) * MAXCH + ci);
    float* pO = g_pO + pbase * 128 * 64;
    #pragma unroll
    for (int nt = 0; nt < 8; nt++) {
        int col = nt*8 + 2*tig;
        *(float2*)(pO + rlo * 64 + col) = make_float2(oc[nt][0], oc[nt][1]);
        *(float2*)(pO + rhi * 64 + col) = make_float2(oc[nt][2], oc[nt][3]);
    }
    if (tig == 0) {
        g_pm[pbase * 128 + rlo] = m_lo;
        g_pm[pbase * 128 + rhi] = m_hi;
        g_pl[pbase * 128 + rlo] = l_lo;
        g_pl[pbase * 128 + rhi] = l_hi;
    }
}

// ---------------------------------------------------------------------------
// Merge: combine <=8 partials per 128-row q-tile, normalize.
// ---------------------------------------------------------------------------
__global__ __launch_bounds__(256) void attn_merge_kernel(float* __restrict__ out)
{
    const int qt = blockIdx.x;
    const int b  = blockIdx.y;
    const int nc = qt / 4 + 1;

    const int t   = threadIdx.x;
    const int row = t >> 1;
    const int c0  = (t & 1) * 32;

    const size_t pbase = (size_t)(b * NQT + qt) * MAXCH;

    float mv[MAXCH], lv[MAXCH];
    float M = -1e30f;
    for (int ci = 0; ci < nc; ci++) {
        mv[ci] = g_pm[(pbase + ci) * 128 + row];
        lv[ci] = g_pl[(pbase + ci) * 128 + row];
        M = fmaxf(M, mv[ci]);
    }
    float L = 0.f;
    for (int ci = 0; ci < nc; ci++) L += lv[ci] * __expf(mv[ci] - M);

    float acc[32] = {};
    for (int ci = 0; ci < nc; ci++) {
        float wgt = __expf(mv[ci] - M);
        const float* pO = g_pO + (pbase + ci) * 128 * 64 + row * 64 + c0;
        #pragma unroll
        for (int u = 0; u < 8; u++) {
            float4 v4 = *(const float4*)(pO + 4*u);
            acc[4*u + 0] += wgt * v4.x;
            acc[4*u + 1] += wgt * v4.y;
            acc[4*u + 2] += wgt * v4.z;
            acc[4*u + 3] += wgt * v4.w;
        }
    }
    float inv = 1.0f / L;
    float* ob = out + ((size_t)b * T_LEN + qt * 128 + row) * D_HEAD + c0;
    #pragma unroll
    for (int u = 0; u < 8; u++)
        *(float4*)(ob + 4*u) = make_float4(acc[4*u + 0] * inv, acc[4*u + 1] * inv,
                                           acc[4*u + 2] * inv, acc[4*u + 3] * inv);
}

// ---------------------------------------------------------------------------
extern "C" void kernel_launch(void* const* d_in, const int* in_sizes, int n_in,
                              void* d_out, int out_size)
{
    (void)in_sizes; (void)n_in; (void)out_size;
    const float* Q  = (const float*)d_in[0];
    const float* K  = (const float*)d_in[1];
    const float* V  = (const float*)d_in[2];
    const float* Wq = (const float*)d_in[3];
    const float* bq = (const float*)d_in[4];
    const float* Wk = (const float*)d_in[5];
    const float* bk = (const float*)d_in[6];
    const float* Wv = (const float*)d_in[7];
    const float* bv = (const float*)d_in[8];

    static bool attr_set = false;
    if (!attr_set) {
        cudaFuncSetAttribute(attn_partial_kernel,
                             cudaFuncAttributeMaxDynamicSharedMemorySize, SMEM_ATTN);
        attr_set = true;
    }

    dim3 pg(M_ROWS / 128, 3);
    proj_kernel<<<pg, 256>>>(Q, K, V, Wq, bq, Wk, bk, Wv, bv);

    dim3 ag(NCTA_B, B_SZ);
    attn_partial_kernel<<<ag, 256, SMEM_ATTN>>>();

    dim3 mg(NQT, B_SZ);
    attn_merge_kernel<<<mg, 256>>>((float*)d_out);
}

// round 11
// speedup vs baseline: 1.0919x; 1.0919x over previous
#include <cuda_runtime.h>
#include <stdint.h>

#define C_DIM  1024
#define D_HEAD 64
#define B_SZ   4
#define T_LEN  4096
#define M_ROWS (B_SZ * T_LEN)
#define NQT    (T_LEN / 128)     // 32 q-tiles (128 rows) per batch
#define CHUNK  8                 // k-tiles (64 wide) per CTA
#define MAXCH  8
#define NCTA_B 144               // sum_{qt=0..31} (qt/4 + 1)

// g_q: [b*T+t][d] tf32 bits, pre-scaled 0.125 (plain layout)
// g_k: [b*T+t][d] tf32 bits, d permuted within 8-blocks (pperm)
// g_v: [tile][d][s] tf32 bits, per-64-tile transposed, s permuted within 8-blocks
__device__ float g_q[M_ROWS * D_HEAD];
__device__ float g_k[M_ROWS * D_HEAD];
__device__ float g_v[M_ROWS * D_HEAD];

// Split-KV partials
__device__ float g_pO[B_SZ * NQT * MAXCH * 128 * 64];
__device__ float g_pm[B_SZ * NQT * MAXCH * 128];
__device__ float g_pl[B_SZ * NQT * MAXCH * 128];

__device__ __forceinline__ int pperm(int c) {           // 0..7 block permute
    return ((c & 3) << 1) | (c >> 2);                   // slots t,t+4 -> 2t,2t+1
}
__device__ __forceinline__ uint32_t f2tf(float x) {
    uint32_t r; asm("cvt.rna.tf32.f32 %0, %1;" : "=r"(r) : "f"(x)); return r;
}
__device__ __forceinline__ uint32_t fb(float x) { return __float_as_uint(x); }

__device__ __forceinline__ void mma_tf32(float c[4],
    uint32_t a0, uint32_t a1, uint32_t a2, uint32_t a3,
    uint32_t b0, uint32_t b1)
{
    asm volatile(
        "mma.sync.aligned.m16n8k8.row.col.f32.tf32.tf32.f32 "
        "{%0,%1,%2,%3}, {%4,%5,%6,%7}, {%8,%9}, {%0,%1,%2,%3};"
        : "+f"(c[0]), "+f"(c[1]), "+f"(c[2]), "+f"(c[3])
        : "r"(a0), "r"(a1), "r"(a2), "r"(a3), "r"(b0), "r"(b1));
}

__device__ __forceinline__ void cp16(float* dst_smem, const float* src) {
    uint32_t d = (uint32_t)__cvta_generic_to_shared(dst_smem);
    asm volatile("cp.async.ca.shared.global [%0], [%1], 16;" :: "r"(d), "l"(src) : "memory");
}
#define CP_COMMIT() asm volatile("cp.async.commit_group;" ::: "memory")
#define CP_WAIT(N)  asm volatile("cp.async.wait_group %0;" :: "n"(N) : "memory")

// ---------------------------------------------------------------------------
// Projection GEMM (tf32 MMA) — round-6 main loop (measured 95us), with
// layout-specific epilogues feeding the attn kernel's permuted layouts.
// 128-row CTAs, 256 threads, 8 warps x (16x64), K-step 32, reg prefetch.
// ---------------------------------------------------------------------------
#define XS_STRIDE 36
#define WS_STRIDE 72

__global__ __launch_bounds__(256) void proj_kernel(
    const float* __restrict__ Xq, const float* __restrict__ Xk, const float* __restrict__ Xv,
    const float* __restrict__ Wq, const float* __restrict__ bq,
    const float* __restrict__ Wk, const float* __restrict__ bk,
    const float* __restrict__ Wv, const float* __restrict__ bv)
{
    __shared__ float Xs[128][XS_STRIDE];
    __shared__ float Ws[32][WS_STRIDE];

    const float* X; const float* W; const float* bias;
    if (blockIdx.y == 0)      { X = Xq; W = Wq; bias = bq; }
    else if (blockIdx.y == 1) { X = Xk; W = Wk; bias = bk; }
    else                      { X = Xv; W = Wv; bias = bv; }

    const int t    = threadIdx.x;
    const int lane = t & 31;
    const int w    = t >> 5;
    const int g    = lane >> 2;
    const int tig  = lane & 3;
    const int m0   = blockIdx.x * 128;

    const int xrow = t >> 1;
    const int xc0  = (t & 1) * 16;
    const int wrow = t >> 3;
    const int wc0  = (t & 7) * 8;

    float4 xv[4], wv[2];
    #pragma unroll
    for (int i = 0; i < 4; i++)
        xv[i] = *(const float4*)(X + (size_t)(m0 + xrow) * C_DIM + xc0 + 4 * i);
    #pragma unroll
    for (int i = 0; i < 2; i++)
        wv[i] = *(const float4*)(W + (size_t)wrow * D_HEAD + wc0 + 4 * i);

    float c[8][4] = {};

    for (int k0 = 0; k0 < C_DIM; k0 += 32) {
        #pragma unroll
        for (int i = 0; i < 4; i++) {
            Xs[xrow][xc0 + 4*i + 0] = __uint_as_float(f2tf(xv[i].x));
            Xs[xrow][xc0 + 4*i + 1] = __uint_as_float(f2tf(xv[i].y));
            Xs[xrow][xc0 + 4*i + 2] = __uint_as_float(f2tf(xv[i].z));
            Xs[xrow][xc0 + 4*i + 3] = __uint_as_float(f2tf(xv[i].w));
        }
        #pragma unroll
        for (int i = 0; i < 2; i++) {
            Ws[wrow][wc0 + 4*i + 0] = __uint_as_float(f2tf(wv[i].x));
            Ws[wrow][wc0 + 4*i + 1] = __uint_as_float(f2tf(wv[i].y));
            Ws[wrow][wc0 + 4*i + 2] = __uint_as_float(f2tf(wv[i].z));
            Ws[wrow][wc0 + 4*i + 3] = __uint_as_float(f2tf(wv[i].w));
        }
        __syncthreads();

        if (k0 + 32 < C_DIM) {
            #pragma unroll
            for (int i = 0; i < 4; i++)
                xv[i] = *(const float4*)(X + (size_t)(m0 + xrow) * C_DIM + k0 + 32 + xc0 + 4 * i);
            #pragma unroll
            for (int i = 0; i < 2; i++)
                wv[i] = *(const float4*)(W + (size_t)(k0 + 32 + wrow) * D_HEAD + wc0 + 4 * i);
        }

        #pragma unroll
        for (int kc = 0; kc < 4; kc++) {
            uint32_t a0 = fb(Xs[w*16 + g    ][kc*8 + tig    ]);
            uint32_t a1 = fb(Xs[w*16 + g + 8][kc*8 + tig    ]);
            uint32_t a2 = fb(Xs[w*16 + g    ][kc*8 + tig + 4]);
            uint32_t a3 = fb(Xs[w*16 + g + 8][kc*8 + tig + 4]);
            #pragma unroll
            for (int nt = 0; nt < 8; nt++) {
                uint32_t b0 = fb(Ws[kc*8 + tig    ][nt*8 + g]);
                uint32_t b1 = fb(Ws[kc*8 + tig + 4][nt*8 + g]);
                mma_tf32(c[nt], a0, a1, a2, a3, b0, b1);
            }
        }
        __syncthreads();
    }

    // Epilogue: bias + layout-specific store
    const int rlo = m0 + w*16 + g;
    const int rhi = rlo + 8;
    if (blockIdx.y == 0) {
        // Q: plain layout, pre-scale 0.125
        #pragma unroll
        for (int nt = 0; nt < 8; nt++) {
            int col = nt*8 + 2*tig;
            float b0 = bias[col], b1 = bias[col + 1];
            *(float2*)(g_q + (size_t)rlo * D_HEAD + col) =
                make_float2(__uint_as_float(f2tf((c[nt][0] + b0) * 0.125f)),
                            __uint_as_float(f2tf((c[nt][1] + b1) * 0.125f)));
            *(float2*)(g_q + (size_t)rhi * D_HEAD + col) =
                make_float2(__uint_as_float(f2tf((c[nt][2] + b0) * 0.125f)),
                            __uint_as_float(f2tf((c[nt][3] + b1) * 0.125f)));
        }
    } else if (blockIdx.y == 1) {
        // K: d-permuted within 8-blocks (same 32B sector -> still coalesced)
        #pragma unroll
        for (int nt = 0; nt < 8; nt++) {
            int col = nt*8 + 2*tig;
            float b0 = bias[col], b1 = bias[col + 1];
            int p0 = nt*8 + pperm((2*tig) & 7);
            int p1 = nt*8 + pperm((2*tig + 1) & 7);
            g_k[(size_t)rlo * D_HEAD + p0] = __uint_as_float(f2tf(c[nt][0] + b0));
            g_k[(size_t)rlo * D_HEAD + p1] = __uint_as_float(f2tf(c[nt][1] + b1));
            g_k[(size_t)rhi * D_HEAD + p0] = __uint_as_float(f2tf(c[nt][2] + b0));
            g_k[(size_t)rhi * D_HEAD + p1] = __uint_as_float(f2tf(c[nt][3] + b1));
        }
    } else {
        // V: [tile][d][s-permuted] transposed layout
        const int tlo = rlo >> 6, slo = rlo & 63;
        const int thi = rhi >> 6, shi = rhi & 63;
        const int splo = (slo & ~7) | pperm(slo & 7);
        const int sphi = (shi & ~7) | pperm(shi & 7);
        #pragma unroll
        for (int nt = 0; nt < 8; nt++) {
            int col = nt*8 + 2*tig;
            float b0 = bias[col], b1 = bias[col + 1];
            g_v[((size_t)tlo*64 + col    )*64 + splo] = __uint_as_float(f2tf(c[nt][0] + b0));
            g_v[((size_t)tlo*64 + col + 1)*64 + splo] = __uint_as_float(f2tf(c[nt][1] + b1));
            g_v[((size_t)thi*64 + col    )*64 + sphi] = __uint_as_float(f2tf(c[nt][2] + b0));
            g_v[((size_t)thi*64 + col + 1)*64 + sphi] = __uint_as_float(f2tf(c[nt][3] + b1));
        }
    }
}

// ---------------------------------------------------------------------------
// Flash attention partial: 128-row q-tile, 256 threads, split-KV <=8 k-tiles.
// K,V double-buffered cp.async (stride 72 -> conflict-free LDS.64 b-frags),
// dedicated P buffer (stride 68), one __syncthreads per iter.
// ---------------------------------------------------------------------------
#define KST 72
#define VST 72
#define PST 68
#define SMEM_ATTN ((2*64*KST + 2*64*VST + 128*PST) * 4)

__global__ __launch_bounds__(256, 2) void attn_partial_kernel()
{
    extern __shared__ float sm[];
    float* ks[2] = { sm, sm + 64*KST };
    float* vs[2] = { sm + 2*64*KST, sm + 2*64*KST + 64*VST };
    float* ps    = sm + 2*64*KST + 2*64*VST;   // [128][PST]

    const int b = blockIdx.y;
    int idx = NCTA_B - 1 - blockIdx.x;   // heavy q-tiles first
    int grp = 0, base = 0;
    while (idx >= base + 4*(grp+1)) { base += 4*(grp+1); ++grp; }
    int r  = idx - base;
    int qt = 4*grp + r / (grp+1);
    int ci = r % (grp+1);
    const int j0   = ci * CHUNK;
    const int jend = min(j0 + CHUNK, 2*qt + 2);

    const int t    = threadIdx.x;
    const int lane = t & 31;
    const int w    = t >> 5;
    const int g    = lane >> 2;
    const int tig  = lane & 3;
    const int rlo  = w*16 + g;
    const int rhi  = rlo + 8;

    const float* qp = g_q + ((size_t)b * T_LEN + qt * 128) * D_HEAD;
    const float* kb = g_k + (size_t)b * T_LEN * D_HEAD;
    const float* vtb = g_v + (size_t)b * 64 * 64 * 64;   // [tile][d][sp] per batch

    const int row = t >> 2;           // 0..63
    const int c0  = (t & 3) * 16;

    // Prologue: K_j0 + V_j0 one group
    {
        const float* kp = kb + (size_t)(j0*64 + row) * D_HEAD + c0;
        const float* vp = vtb + ((size_t)j0*64 + row) * 64 + c0;
        #pragma unroll
        for (int i = 0; i < 4; i++) cp16(ks[0] + row*KST + c0 + 4*i, kp + 4*i);
        #pragma unroll
        for (int i = 0; i < 4; i++) cp16(vs[0] + row*VST + c0 + 4*i, vp + 4*i);
        CP_COMMIT();
    }

    // Q fragments (tf32 bits, pre-scaled)
    uint32_t qa[8][4];
    #pragma unroll
    for (int kc = 0; kc < 8; kc++) {
        qa[kc][0] = fb(qp[rlo * D_HEAD + kc*8 + tig    ]);
        qa[kc][1] = fb(qp[rhi * D_HEAD + kc*8 + tig    ]);
        qa[kc][2] = fb(qp[rlo * D_HEAD + kc*8 + tig + 4]);
        qa[kc][3] = fb(qp[rhi * D_HEAD + kc*8 + tig + 4]);
    }

    float oc[8][4] = {};
    float m_lo = -1e30f, m_hi = -1e30f, l_lo = 0.f, l_hi = 0.f;

    for (int j = j0; j < jend; j++) {
        const int bufc = (j - j0) & 1;
        float* kcur = ks[bufc];
        float* vcur = vs[bufc];

        CP_WAIT(0);
        __syncthreads();

        if (j + 1 < jend) {
            float* knxt = ks[bufc ^ 1];
            float* vnxt = vs[bufc ^ 1];
            const float* kp = kb + (size_t)((j+1)*64 + row) * D_HEAD + c0;
            const float* vp = vtb + ((size_t)(j+1)*64 + row) * 64 + c0;
            #pragma unroll
            for (int i = 0; i < 4; i++) cp16(knxt + row*KST + c0 + 4*i, kp + 4*i);
            #pragma unroll
            for (int i = 0; i < 4; i++) cp16(vnxt + row*VST + c0 + 4*i, vp + 4*i);
            CP_COMMIT();
        }

        // S = Q @ K^T  (b-frags: one LDS.64 each, conflict-free)
        float sc[8][4] = {};
        #pragma unroll
        for (int kc = 0; kc < 8; kc++) {
            #pragma unroll
            for (int nt = 0; nt < 8; nt++) {
                float2 bbv = *(const float2*)&kcur[(nt*8 + g)*KST + kc*8 + 2*tig];
                mma_tf32(sc[nt], qa[kc][0], qa[kc][1], qa[kc][2], qa[kc][3],
                         fb(bbv.x), fb(bbv.y));
            }
        }

        // Causal mask (k-tiles j >= 2*qt touch the diagonal)
        if (j >= 2*qt) {
            const int co = (j - 2*qt) * 64;
            #pragma unroll
            for (int nt = 0; nt < 8; nt++) {
                int cb = co + nt*8 + 2*tig;
                if (cb     > rlo) sc[nt][0] = -1e30f;
                if (cb + 1 > rlo) sc[nt][1] = -1e30f;
                if (cb     > rhi) sc[nt][2] = -1e30f;
                if (cb + 1 > rhi) sc[nt][3] = -1e30f;
            }
        }

        // Online softmax
        float mx0 = -1e30f, mx1 = -1e30f;
        #pragma unroll
        for (int nt = 0; nt < 8; nt++) {
            mx0 = fmaxf(mx0, fmaxf(sc[nt][0], sc[nt][1]));
            mx1 = fmaxf(mx1, fmaxf(sc[nt][2], sc[nt][3]));
        }
        mx0 = fmaxf(mx0, __shfl_xor_sync(0xffffffffu, mx0, 1));
        mx0 = fmaxf(mx0, __shfl_xor_sync(0xffffffffu, mx0, 2));
        mx1 = fmaxf(mx1, __shfl_xor_sync(0xffffffffu, mx1, 1));
        mx1 = fmaxf(mx1, __shfl_xor_sync(0xffffffffu, mx1, 2));

        float mn0 = fmaxf(m_lo, mx0);
        float mn1 = fmaxf(m_hi, mx1);
        float s0 = 0.f, s1 = 0.f;
        #pragma unroll
        for (int nt = 0; nt < 8; nt++) {
            sc[nt][0] = __expf(sc[nt][0] - mn0); s0 += sc[nt][0];
            sc[nt][1] = __expf(sc[nt][1] - mn0); s0 += sc[nt][1];
            sc[nt][2] = __expf(sc[nt][2] - mn1); s1 += sc[nt][2];
            sc[nt][3] = __expf(sc[nt][3] - mn1); s1 += sc[nt][3];
        }
        s0 += __shfl_xor_sync(0xffffffffu, s0, 1);
        s0 += __shfl_xor_sync(0xffffffffu, s0, 2);
        s1 += __shfl_xor_sync(0xffffffffu, s1, 1);
        s1 += __shfl_xor_sync(0xffffffffu, s1, 2);

        float a0 = __expf(m_lo - mn0);
        float a1 = __expf(m_hi - mn1);
        l_lo = l_lo * a0 + s0;  m_lo = mn0;
        l_hi = l_hi * a1 + s1;  m_hi = mn1;
        #pragma unroll
        for (int nt = 0; nt < 8; nt++) {
            oc[nt][0] *= a0; oc[nt][1] *= a0;
            oc[nt][2] *= a1; oc[nt][3] *= a1;
        }

        // P -> ps (per-warp strip, plain s order)
        {
            float* plo = ps + rlo*PST;
            float* phi = ps + rhi*PST;
            #pragma unroll
            for (int nt = 0; nt < 8; nt++) {
                int cb = nt*8 + 2*tig;
                *(float2*)&plo[cb] = make_float2(__uint_as_float(f2tf(sc[nt][0])),
                                                 __uint_as_float(f2tf(sc[nt][1])));
                *(float2*)&phi[cb] = make_float2(__uint_as_float(f2tf(sc[nt][2])),
                                                 __uint_as_float(f2tf(sc[nt][3])));
            }
        }
        __syncwarp();

        // O += P @ V  (V b-frags: one LDS.64 via transposed+permuted layout)
        #pragma unroll
        for (int kc = 0; kc < 8; kc++) {
            uint32_t pa0 = fb(ps[rlo*PST + kc*8 + tig    ]);
            uint32_t pa1 = fb(ps[rhi*PST + kc*8 + tig    ]);
            uint32_t pa2 = fb(ps[rlo*PST + kc*8 + tig + 4]);
            uint32_t pa3 = fb(ps[rhi*PST + kc*8 + tig + 4]);
            #pragma unroll
            for (int nt = 0; nt < 8; nt++) {
                float2 bbv = *(const float2*)&vcur[(nt*8 + g)*VST + kc*8 + 2*tig];
                mma_tf32(oc[nt], pa0, pa1, pa2, pa3, fb(bbv.x), fb(bbv.y));
            }
        }
    }

    // Write partial + m/l
    const size_t pbase = ((size_t)(b * NQT + qt) * MAXCH + ci);
    float* pO = g_pO + pbase * 128 * 64;
    #pragma unroll
    for (int nt = 0; nt < 8; nt++) {
        int col = nt*8 + 2*tig;
        *(float2*)(pO + rlo * 64 + col) = make_float2(oc[nt][0], oc[nt][1]);
        *(float2*)(pO + rhi * 64 + col) = make_float2(oc[nt][2], oc[nt][3]);
    }
    if (tig == 0) {
        g_pm[pbase * 128 + rlo] = m_lo;
        g_pm[pbase * 128 + rhi] = m_hi;
        g_pl[pbase * 128 + rlo] = l_lo;
        g_pl[pbase * 128 + rhi] = l_hi;
    }
}

// ---------------------------------------------------------------------------
// Merge: combine <=8 partials per 128-row q-tile, normalize.
// ---------------------------------------------------------------------------
__global__ __launch_bounds__(256) void attn_merge_kernel(float* __restrict__ out)
{
    const int qt = blockIdx.x;
    const int b  = blockIdx.y;
    const int nc = qt / 4 + 1;

    const int t   = threadIdx.x;
    const int row = t >> 1;
    const int c0  = (t & 1) * 32;

    const size_t pbase = (size_t)(b * NQT + qt) * MAXCH;

    float mv[MAXCH], lv[MAXCH];
    float M = -1e30f;
    for (int ci = 0; ci < nc; ci++) {
        mv[ci] = g_pm[(pbase + ci) * 128 + row];
        lv[ci] = g_pl[(pbase + ci) * 128 + row];
        M = fmaxf(M, mv[ci]);
    }
    float L = 0.f;
    for (int ci = 0; ci < nc; ci++) L += lv[ci] * __expf(mv[ci] - M);

    float acc[32] = {};
    for (int ci = 0; ci < nc; ci++) {
        float wgt = __expf(mv[ci] - M);
        const float* pO = g_pO + (pbase + ci) * 128 * 64 + row * 64 + c0;
        #pragma unroll
        for (int u = 0; u < 8; u++) {
            float4 v4 = *(const float4*)(pO + 4*u);
            acc[4*u + 0] += wgt * v4.x;
            acc[4*u + 1] += wgt * v4.y;
            acc[4*u + 2] += wgt * v4.z;
            acc[4*u + 3] += wgt * v4.w;
        }
    }
    float inv = 1.0f / L;
    float* ob = out + ((size_t)b * T_LEN + qt * 128 + row) * D_HEAD + c0;
    #pragma unroll
    for (int u = 0; u < 8; u++)
        *(float4*)(ob + 4*u) = make_float4(acc[4*u + 0] * inv, acc[4*u + 1] * inv,
                                           acc[4*u + 2] * inv, acc[4*u + 3] * inv);
}

// ---------------------------------------------------------------------------
extern "C" void kernel_launch(void* const* d_in, const int* in_sizes, int n_in,
                              void* d_out, int out_size)
{
    (void)in_sizes; (void)n_in; (void)out_size;
    const float* Q  = (const float*)d_in[0];
    const float* K  = (const float*)d_in[1];
    const float* V  = (const float*)d_in[2];
    const float* Wq = (const float*)d_in[3];
    const float* bq = (const float*)d_in[4];
    const float* Wk = (const float*)d_in[5];
    const float* bk = (const float*)d_in[6];
    const float* Wv = (const float*)d_in[7];
    const float* bv = (const float*)d_in[8];

    static bool attr_set = false;
    if (!attr_set) {
        cudaFuncSetAttribute(attn_partial_kernel,
                             cudaFuncAttributeMaxDynamicSharedMemorySize, SMEM_ATTN);
        attr_set = true;
    }

    dim3 pg(M_ROWS / 128, 3);
    proj_kernel<<<pg, 256>>>(Q, K, V, Wq, bq, Wk, bk, Wv, bv);

    dim3 ag(NCTA_B, B_SZ);
    attn_partial_kernel<<<ag, 256, SMEM_ATTN>>>();

    dim3 mg(NQT, B_SZ);
    attn_merge_kernel<<<mg, 256>>>((float*)d_out);
}

// round 13
// speedup vs baseline: 1.6425x; 1.5043x over previous
#include <cuda_runtime.h>
#include <stdint.h>

#define C_DIM  1024
#define D_HEAD 64
#define B_SZ   4
#define T_LEN  4096
#define M_ROWS (B_SZ * T_LEN)
#define NQT    (T_LEN / 128)     // 32 q-tiles (128 rows) per batch
#define CHUNK  8                 // k-tiles (64 wide) per CTA
#define MAXCH  8
#define NCTA_B 144               // sum_{qt=0..31} (qt/4 + 1)

// g_q: [b*T+t][d] tf32 bits, pre-scaled 0.125 (plain layout)
// g_k: [b*T+t][d] tf32 bits, d permuted within 8-blocks (pperm)
// g_v: [tile][d][s] tf32 bits, per-64-tile transposed, s permuted within 8-blocks
__device__ float g_q[M_ROWS * D_HEAD];
__device__ float g_k[M_ROWS * D_HEAD];
__device__ float g_v[M_ROWS * D_HEAD];

// Split-KV partials
__device__ float g_pO[B_SZ * NQT * MAXCH * 128 * 64];
__device__ float g_pm[B_SZ * NQT * MAXCH * 128];
__device__ float g_pl[B_SZ * NQT * MAXCH * 128];

__device__ __forceinline__ int pperm(int c) {           // 0..7 block permute
    return ((c & 3) << 1) | (c >> 2);                   // slots t,t+4 -> 2t,2t+1
}
__device__ __forceinline__ uint32_t f2tf(float x) {
    uint32_t r; asm("cvt.rna.tf32.f32 %0, %1;" : "=r"(r) : "f"(x)); return r;
}
__device__ __forceinline__ uint32_t fb(float x) { return __float_as_uint(x); }

__device__ __forceinline__ void mma_tf32(float c[4],
    uint32_t a0, uint32_t a1, uint32_t a2, uint32_t a3,
    uint32_t b0, uint32_t b1)
{
    asm volatile(
        "mma.sync.aligned.m16n8k8.row.col.f32.tf32.tf32.f32 "
        "{%0,%1,%2,%3}, {%4,%5,%6,%7}, {%8,%9}, {%0,%1,%2,%3};"
        : "+f"(c[0]), "+f"(c[1]), "+f"(c[2]), "+f"(c[3])
        : "r"(a0), "r"(a1), "r"(a2), "r"(a3), "r"(b0), "r"(b1));
}

__device__ __forceinline__ void cp16(float* dst_smem, const float* src) {
    uint32_t d = (uint32_t)__cvta_generic_to_shared(dst_smem);
    asm volatile("cp.async.ca.shared.global [%0], [%1], 16;" :: "r"(d), "l"(src) : "memory");
}
#define CP_COMMIT() asm volatile("cp.async.commit_group;" ::: "memory")
#define CP_WAIT(N)  asm volatile("cp.async.wait_group %0;" :: "n"(N) : "memory")

// ---------------------------------------------------------------------------
// Projection GEMM (tf32 MMA) — round-6 main loop, layout epilogues.
// V epilogue stages through smem (scalar stores — odd stride, so no float2
// on the permuted-row side) then does a coalesced float2 writeout of g_v.
// Shared pool aliases: Xs[128][36]+Ws[32][72] (6912 floats) vs T[128][65].
// ---------------------------------------------------------------------------
#define XS_STRIDE 36
#define WS_STRIDE 72
#define TST 65
#define POOL_FLOATS (128 * TST)   // 8320 >= 6912

__global__ __launch_bounds__(256) void proj_kernel(
    const float* __restrict__ Xq, const float* __restrict__ Xk, const float* __restrict__ Xv,
    const float* __restrict__ Wq, const float* __restrict__ bq,
    const float* __restrict__ Wk, const float* __restrict__ bk,
    const float* __restrict__ Wv, const float* __restrict__ bv)
{
    __shared__ float pool[POOL_FLOATS];
    float (*Xs)[XS_STRIDE] = (float (*)[XS_STRIDE])pool;
    float (*Ws)[WS_STRIDE] = (float (*)[WS_STRIDE])(pool + 128 * XS_STRIDE);

    const float* X; const float* W; const float* bias;
    if (blockIdx.y == 0)      { X = Xq; W = Wq; bias = bq; }
    else if (blockIdx.y == 1) { X = Xk; W = Wk; bias = bk; }
    else                      { X = Xv; W = Wv; bias = bv; }

    const int t    = threadIdx.x;
    const int lane = t & 31;
    const int w    = t >> 5;
    const int g    = lane >> 2;
    const int tig  = lane & 3;
    const int m0   = blockIdx.x * 128;

    const int xrow = t >> 1;
    const int xc0  = (t & 1) * 16;
    const int wrow = t >> 3;
    const int wc0  = (t & 7) * 8;

    float4 xv[4], wv[2];
    #pragma unroll
    for (int i = 0; i < 4; i++)
        xv[i] = *(const float4*)(X + (size_t)(m0 + xrow) * C_DIM + xc0 + 4 * i);
    #pragma unroll
    for (int i = 0; i < 2; i++)
        wv[i] = *(const float4*)(W + (size_t)wrow * D_HEAD + wc0 + 4 * i);

    float c[8][4] = {};

    for (int k0 = 0; k0 < C_DIM; k0 += 32) {
        #pragma unroll
        for (int i = 0; i < 4; i++) {
            Xs[xrow][xc0 + 4*i + 0] = __uint_as_float(f2tf(xv[i].x));
            Xs[xrow][xc0 + 4*i + 1] = __uint_as_float(f2tf(xv[i].y));
            Xs[xrow][xc0 + 4*i + 2] = __uint_as_float(f2tf(xv[i].z));
            Xs[xrow][xc0 + 4*i + 3] = __uint_as_float(f2tf(xv[i].w));
        }
        #pragma unroll
        for (int i = 0; i < 2; i++) {
            Ws[wrow][wc0 + 4*i + 0] = __uint_as_float(f2tf(wv[i].x));
            Ws[wrow][wc0 + 4*i + 1] = __uint_as_float(f2tf(wv[i].y));
            Ws[wrow][wc0 + 4*i + 2] = __uint_as_float(f2tf(wv[i].z));
            Ws[wrow][wc0 + 4*i + 3] = __uint_as_float(f2tf(wv[i].w));
        }
        __syncthreads();

        if (k0 + 32 < C_DIM) {
            #pragma unroll
            for (int i = 0; i < 4; i++)
                xv[i] = *(const float4*)(X + (size_t)(m0 + xrow) * C_DIM + k0 + 32 + xc0 + 4 * i);
            #pragma unroll
            for (int i = 0; i < 2; i++)
                wv[i] = *(const float4*)(W + (size_t)(k0 + 32 + wrow) * D_HEAD + wc0 + 4 * i);
        }

        #pragma unroll
        for (int kc = 0; kc < 4; kc++) {
            uint32_t a0 = fb(Xs[w*16 + g    ][kc*8 + tig    ]);
            uint32_t a1 = fb(Xs[w*16 + g + 8][kc*8 + tig    ]);
            uint32_t a2 = fb(Xs[w*16 + g    ][kc*8 + tig + 4]);
            uint32_t a3 = fb(Xs[w*16 + g + 8][kc*8 + tig + 4]);
            #pragma unroll
            for (int nt = 0; nt < 8; nt++) {
                uint32_t b0 = fb(Ws[kc*8 + tig    ][nt*8 + g]);
                uint32_t b1 = fb(Ws[kc*8 + tig + 4][nt*8 + g]);
                mma_tf32(c[nt], a0, a1, a2, a3, b0, b1);
            }
        }
        __syncthreads();
    }

    // Epilogue: bias + layout-specific store
    const int rlo = m0 + w*16 + g;
    const int rhi = rlo + 8;
    if (blockIdx.y == 0) {
        // Q: plain layout, pre-scale 0.125
        #pragma unroll
        for (int nt = 0; nt < 8; nt++) {
            int col = nt*8 + 2*tig;
            float b0 = bias[col], b1 = bias[col + 1];
            *(float2*)(g_q + (size_t)rlo * D_HEAD + col) =
                make_float2(__uint_as_float(f2tf((c[nt][0] + b0) * 0.125f)),
                            __uint_as_float(f2tf((c[nt][1] + b1) * 0.125f)));
            *(float2*)(g_q + (size_t)rhi * D_HEAD + col) =
                make_float2(__uint_as_float(f2tf((c[nt][2] + b0) * 0.125f)),
                            __uint_as_float(f2tf((c[nt][3] + b1) * 0.125f)));
        }
    } else if (blockIdx.y == 1) {
        // K: d-permuted within 8-blocks (stays in-sector -> coalesced)
        #pragma unroll
        for (int nt = 0; nt < 8; nt++) {
            int col = nt*8 + 2*tig;
            float b0 = bias[col], b1 = bias[col + 1];
            int p0 = nt*8 + pperm((2*tig) & 7);
            int p1 = nt*8 + pperm((2*tig + 1) & 7);
            g_k[(size_t)rlo * D_HEAD + p0] = __uint_as_float(f2tf(c[nt][0] + b0));
            g_k[(size_t)rlo * D_HEAD + p1] = __uint_as_float(f2tf(c[nt][1] + b1));
            g_k[(size_t)rhi * D_HEAD + p0] = __uint_as_float(f2tf(c[nt][2] + b0));
            g_k[(size_t)rhi * D_HEAD + p1] = __uint_as_float(f2tf(c[nt][3] + b1));
        }
    } else {
        // V: stage into smem T[sp][d] (scalar stores: rows at odd float
        // offsets, so float2 would be misaligned), then coalesced writeout.
        float (*T)[TST] = (float (*)[TST])pool;
        const int llo = w*16 + g;          // local row 0..127
        const int lhi = llo + 8;
        const int stlo = (llo & ~7) | pperm(llo & 7);
        const int sthi = (lhi & ~7) | pperm(lhi & 7);
        #pragma unroll
        for (int nt = 0; nt < 8; nt++) {
            int col = nt*8 + 2*tig;
            float b0 = bias[col], b1 = bias[col + 1];
            T[stlo][col    ] = __uint_as_float(f2tf(c[nt][0] + b0));
            T[stlo][col + 1] = __uint_as_float(f2tf(c[nt][1] + b1));
            T[sthi][col    ] = __uint_as_float(f2tf(c[nt][2] + b0));
            T[sthi][col + 1] = __uint_as_float(f2tf(c[nt][3] + b1));
        }
        __syncthreads();
        // Writeout: 128 (tile,d) rows of 64 floats; warp w takes rows
        // w*16..w*16+15; lane covers s = 2*lane, 2*lane+1 -> STG.64, 256B/warp.
        const int gt0 = m0 >> 6;           // first global tile of this CTA
        #pragma unroll
        for (int i = 0; i < 16; i++) {
            int rid  = w*16 + i;           // 0..127
            int tloc = rid >> 6;           // 0 or 1
            int d    = rid & 63;
            float v0 = T[tloc*64 + 2*lane    ][d];
            float v1 = T[tloc*64 + 2*lane + 1][d];
            *(float2*)(g_v + ((size_t)(gt0 + tloc)*64 + d)*64 + 2*lane) =
                make_float2(v0, v1);
        }
    }
}

// ---------------------------------------------------------------------------
// Flash attention partial: 128-row q-tile, 256 threads, split-KV <=8 k-tiles.
// K,V double-buffered cp.async (stride 72 -> conflict-free LDS.64 b-frags),
// dedicated P buffer (stride 68), one __syncthreads per iter.
// ---------------------------------------------------------------------------
#define KST 72
#define VST 72
#define PST 68
#define SMEM_ATTN ((2*64*KST + 2*64*VST + 128*PST) * 4)

__global__ __launch_bounds__(256, 2) void attn_partial_kernel()
{
    extern __shared__ float sm[];
    float* ks[2] = { sm, sm + 64*KST };
    float* vs[2] = { sm + 2*64*KST, sm + 2*64*KST + 64*VST };
    float* ps    = sm + 2*64*KST + 2*64*VST;   // [128][PST]

    const int b = blockIdx.y;
    int idx = NCTA_B - 1 - blockIdx.x;   // heavy q-tiles first
    int grp = 0, base = 0;
    while (idx >= base + 4*(grp+1)) { base += 4*(grp+1); ++grp; }
    int r  = idx - base;
    int qt = 4*grp + r / (grp+1);
    int ci = r % (grp+1);
    const int j0   = ci * CHUNK;
    const int jend = min(j0 + CHUNK, 2*qt + 2);

    const int t    = threadIdx.x;
    const int lane = t & 31;
    const int w    = t >> 5;
    const int g    = lane >> 2;
    const int tig  = lane & 3;
    const int rlo  = w*16 + g;
    const int rhi  = rlo + 8;

    const float* qp = g_q + ((size_t)b * T_LEN + qt * 128) * D_HEAD;
    const float* kb = g_k + (size_t)b * T_LEN * D_HEAD;
    const float* vtb = g_v + (size_t)b * 64 * 64 * 64;   // [tile][d][sp] per batch

    const int row = t >> 2;           // 0..63
    const int c0  = (t & 3) * 16;

    // Prologue: K_j0 + V_j0 one group
    {
        const float* kp = kb + (size_t)(j0*64 + row) * D_HEAD + c0;
        const float* vp = vtb + ((size_t)j0*64 + row) * 64 + c0;
        #pragma unroll
        for (int i = 0; i < 4; i++) cp16(ks[0] + row*KST + c0 + 4*i, kp + 4*i);
        #pragma unroll
        for (int i = 0; i < 4; i++) cp16(vs[0] + row*VST + c0 + 4*i, vp + 4*i);
        CP_COMMIT();
    }

    // Q fragments (tf32 bits, pre-scaled)
    uint32_t qa[8][4];
    #pragma unroll
    for (int kc = 0; kc < 8; kc++) {
        qa[kc][0] = fb(qp[rlo * D_HEAD + kc*8 + tig    ]);
        qa[kc][1] = fb(qp[rhi * D_HEAD + kc*8 + tig    ]);
        qa[kc][2] = fb(qp[rlo * D_HEAD + kc*8 + tig + 4]);
        qa[kc][3] = fb(qp[rhi * D_HEAD + kc*8 + tig + 4]);
    }

    float oc[8][4] = {};
    float m_lo = -1e30f, m_hi = -1e30f, l_lo = 0.f, l_hi = 0.f;

    for (int j = j0; j < jend; j++) {
        const int bufc = (j - j0) & 1;
        float* kcur = ks[bufc];
        float* vcur = vs[bufc];

        CP_WAIT(0);
        __syncthreads();

        if (j + 1 < jend) {
            float* knxt = ks[bufc ^ 1];
            float* vnxt = vs[bufc ^ 1];
            const float* kp = kb + (size_t)((j+1)*64 + row) * D_HEAD + c0;
            const float* vp = vtb + ((size_t)(j+1)*64 + row) * 64 + c0;
            #pragma unroll
            for (int i = 0; i < 4; i++) cp16(knxt + row*KST + c0 + 4*i, kp + 4*i);
            #pragma unroll
            for (int i = 0; i < 4; i++) cp16(vnxt + row*VST + c0 + 4*i, vp + 4*i);
            CP_COMMIT();
        }

        // S = Q @ K^T  (b-frags: one LDS.64 each, conflict-free)
        float sc[8][4] = {};
        #pragma unroll
        for (int kc = 0; kc < 8; kc++) {
            #pragma unroll
            for (int nt = 0; nt < 8; nt++) {
                float2 bbv = *(const float2*)&kcur[(nt*8 + g)*KST + kc*8 + 2*tig];
                mma_tf32(sc[nt], qa[kc][0], qa[kc][1], qa[kc][2], qa[kc][3],
                         fb(bbv.x), fb(bbv.y));
            }
        }

        // Causal mask (k-tiles j >= 2*qt touch the diagonal)
        if (j >= 2*qt) {
            const int co = (j - 2*qt) * 64;
            #pragma unroll
            for (int nt = 0; nt < 8; nt++) {
                int cb = co + nt*8 + 2*tig;
                if (cb     > rlo) sc[nt][0] = -1e30f;
                if (cb + 1 > rlo) sc[nt][1] = -1e30f;
                if (cb     > rhi) sc[nt][2] = -1e30f;
                if (cb + 1 > rhi) sc[nt][3] = -1e30f;
            }
        }

        // Online softmax
        float mx0 = -1e30f, mx1 = -1e30f;
        #pragma unroll
        for (int nt = 0; nt < 8; nt++) {
            mx0 = fmaxf(mx0, fmaxf(sc[nt][0], sc[nt][1]));
            mx1 = fmaxf(mx1, fmaxf(sc[nt][2], sc[nt][3]));
        }
        mx0 = fmaxf(mx0, __shfl_xor_sync(0xffffffffu, mx0, 1));
        mx0 = fmaxf(mx0, __shfl_xor_sync(0xffffffffu, mx0, 2));
        mx1 = fmaxf(mx1, __shfl_xor_sync(0xffffffffu, mx1, 1));
        mx1 = fmaxf(mx1, __shfl_xor_sync(0xffffffffu, mx1, 2));

        float mn0 = fmaxf(m_lo, mx0);
        float mn1 = fmaxf(m_hi, mx1);
        float s0 = 0.f, s1 = 0.f;
        #pragma unroll
        for (int nt = 0; nt < 8; nt++) {
            sc[nt][0] = __expf(sc[nt][0] - mn0); s0 += sc[nt][0];
            sc[nt][1] = __expf(sc[nt][1] - mn0); s0 += sc[nt][1];
            sc[nt][2] = __expf(sc[nt][2] - mn1); s1 += sc[nt][2];
            sc[nt][3] = __expf(sc[nt][3] - mn1); s1 += sc[nt][3];
        }
        s0 += __shfl_xor_sync(0xffffffffu, s0, 1);
        s0 += __shfl_xor_sync(0xffffffffu, s0, 2);
        s1 += __shfl_xor_sync(0xffffffffu, s1, 1);
        s1 += __shfl_xor_sync(0xffffffffu, s1, 2);

        float a0 = __expf(m_lo - mn0);
        float a1 = __expf(m_hi - mn1);
        l_lo = l_lo * a0 + s0;  m_lo = mn0;
        l_hi = l_hi * a1 + s1;  m_hi = mn1;
        #pragma unroll
        for (int nt = 0; nt < 8; nt++) {
            oc[nt][0] *= a0; oc[nt][1] *= a0;
            oc[nt][2] *= a1; oc[nt][3] *= a1;
        }

        // P -> ps (per-warp strip, plain s order)
        {
            float* plo = ps + rlo*PST;
            float* phi = ps + rhi*PST;
            #pragma unroll
            for (int nt = 0; nt < 8; nt++) {
                int cb = nt*8 + 2*tig;
                *(float2*)&plo[cb] = make_float2(__uint_as_float(f2tf(sc[nt][0])),
                                                 __uint_as_float(f2tf(sc[nt][1])));
                *(float2*)&phi[cb] = make_float2(__uint_as_float(f2tf(sc[nt][2])),
                                                 __uint_as_float(f2tf(sc[nt][3])));
            }
        }
        __syncwarp();

        // O += P @ V  (V b-frags: one LDS.64 via transposed+permuted layout)
        #pragma unroll
        for (int kc = 0; kc < 8; kc++) {
            uint32_t pa0 = fb(ps[rlo*PST + kc*8 + tig    ]);
            uint32_t pa1 = fb(ps[rhi*PST + kc*8 + tig    ]);
            uint32_t pa2 = fb(ps[rlo*PST + kc*8 + tig + 4]);
            uint32_t pa3 = fb(ps[rhi*PST + kc*8 + tig + 4]);
            #pragma unroll
            for (int nt = 0; nt < 8; nt++) {
                float2 bbv = *(const float2*)&vcur[(nt*8 + g)*VST + kc*8 + 2*tig];
                mma_tf32(oc[nt], pa0, pa1, pa2, pa3, fb(bbv.x), fb(bbv.y));
            }
        }
    }

    // Write partial + m/l
    const size_t pbase = ((size_t)(b * NQT + qt) * MAXCH + ci);
    float* pO = g_pO + pbase * 128 * 64;
    #pragma unroll
    for (int nt = 0; nt < 8; nt++) {
        int col = nt*8 + 2*tig;
        *(float2*)(pO + rlo * 64 + col) = make_float2(oc[nt][0], oc[nt][1]);
        *(float2*)(pO + rhi * 64 + col) = make_float2(oc[nt][2], oc[nt][3]);
    }
    if (tig == 0) {
        g_pm[pbase * 128 + rlo] = m_lo;
        g_pm[pbase * 128 + rhi] = m_hi;
        g_pl[pbase * 128 + rlo] = l_lo;
        g_pl[pbase * 128 + rhi] = l_hi;
    }
}

// ---------------------------------------------------------------------------
// Merge: combine <=8 partials per 128-row q-tile, normalize.
// ---------------------------------------------------------------------------
__global__ __launch_bounds__(256) void attn_merge_kernel(float* __restrict__ out)
{
    const int qt = blockIdx.x;
    const int b  = blockIdx.y;
    const int nc = qt / 4 + 1;

    const int t   = threadIdx.x;
    const int row = t >> 1;
    const int c0  = (t & 1) * 32;

    const size_t pbase = (size_t)(b * NQT + qt) * MAXCH;

    float mv[MAXCH], lv[MAXCH];
    float M = -1e30f;
    for (int ci = 0; ci < nc; ci++) {
        mv[ci] = g_pm[(pbase + ci) * 128 + row];
        lv[ci] = g_pl[(pbase + ci) * 128 + row];
        M = fmaxf(M, mv[ci]);
    }
    float L = 0.f;
    for (int ci = 0; ci < nc; ci++) L += lv[ci] * __expf(mv[ci] - M);

    float acc[32] = {};
    for (int ci = 0; ci < nc; ci++) {
        float wgt = __expf(mv[ci] - M);
        const float* pO = g_pO + (pbase + ci) * 128 * 64 + row * 64 + c0;
        #pragma unroll
        for (int u = 0; u < 8; u++) {
            float4 v4 = *(const float4*)(pO + 4*u);
            acc[4*u + 0] += wgt * v4.x;
            acc[4*u + 1] += wgt * v4.y;
            acc[4*u + 2] += wgt * v4.z;
            acc[4*u + 3] += wgt * v4.w;
        }
    }
    float inv = 1.0f / L;
    float* ob = out + ((size_t)b * T_LEN + qt * 128 + row) * D_HEAD + c0;
    #pragma unroll
    for (int u = 0; u < 8; u++)
        *(float4*)(ob + 4*u) = make_float4(acc[4*u + 0] * inv, acc[4*u + 1] * inv,
                                           acc[4*u + 2] * inv, acc[4*u + 3] * inv);
}

// ---------------------------------------------------------------------------
extern "C" void kernel_launch(void* const* d_in, const int* in_sizes, int n_in,
                              void* d_out, int out_size)
{
    (void)in_sizes; (void)n_in; (void)out_size;
    const float* Q  = (const float*)d_in[0];
    const float* K  = (const float*)d_in[1];
    const float* V  = (const float*)d_in[2];
    const float* Wq = (const float*)d_in[3];
    const float* bq = (const float*)d_in[4];
    const float* Wk = (const float*)d_in[5];
    const float* bk = (const float*)d_in[6];
    const float* Wv = (const float*)d_in[7];
    const float* bv = (const float*)d_in[8];

    static bool attr_set = false;
    if (!attr_set) {
        cudaFuncSetAttribute(attn_partial_kernel,
                             cudaFuncAttributeMaxDynamicSharedMemorySize, SMEM_ATTN);
        attr_set = true;
    }

    dim3 pg(M_ROWS / 128, 3);
    proj_kernel<<<pg, 256>>>(Q, K, V, Wq, bq, Wk, bk, Wv, bv);

    dim3 ag(NCTA_B, B_SZ);
    attn_partial_kernel<<<ag, 256, SMEM_ATTN>>>();

    dim3 mg(NQT, B_SZ);
    attn_merge_kernel<<<mg, 256>>>((float*)d_out);
}